// round 16
// baseline (speedup 1.0000x reference)
#include <cuda_runtime.h>
#include <cuda_bf16.h>
#include <cstdint>
#include <math.h>

// ---------------------------------------------------------------------------
// SelectiveSSM (Mamba-style block) — split-bf16 HMMA GEMMs, cp.async pipeline
//   B=2, L=2048, d_model=1024, d_inner=2048, d_state=16, d_conv=4
// R15: R14 + bc fused into delta-GEMM launch (tail fill), fp32 xconv dropped
// (consumers reconstruct hi+lo), transpose merged into preproc, __expf paths.
// ---------------------------------------------------------------------------

#define BATCH  2
#define SEQ    2048
#define DM     1024
#define DI     2048
#define DS     16
#define DC     4
#define CHUNK  128
#define NCH    (SEQ / CHUNK)    // 16
#define MTOT   (BATCH * SEQ)    // 4096

typedef __nv_bfloat16  bf16;
typedef __nv_bfloat162 bf162;

// ------------------------- scratch (static, no mallocs) -------------------
__device__ float g_xz   [(size_t)MTOT * 2 * DI];
__device__ float g_delta[(size_t)MTOT * DI];
__device__ float g_bc   [(size_t)MTOT * 2 * DS];          // B,C cols (fp32)
__device__ float g_chA  [(size_t)BATCH * NCH * DI * DS];
__device__ float g_chH  [(size_t)BATCH * NCH * DI * DS];
__device__ float g_hInit[(size_t)BATCH * NCH * DI * DS];

// bf16 hi/lo operand buffers
__device__ __align__(16) bf16 g_x_hi    [(size_t)MTOT * DM];
__device__ __align__(16) bf16 g_x_lo    [(size_t)MTOT * DM];
__device__ __align__(16) bf16 g_Win_hi  [(size_t)(2*DI) * DM];
__device__ __align__(16) bf16 g_Win_lo  [(size_t)(2*DI) * DM];
__device__ __align__(16) bf16 g_Wdt_hi  [(size_t)DI * DI];
__device__ __align__(16) bf16 g_Wdt_lo  [(size_t)DI * DI];
__device__ __align__(16) bf16 g_Wout_hi [(size_t)DM * DI];
__device__ __align__(16) bf16 g_Wout_lo [(size_t)DM * DI];
__device__ __align__(16) bf16 g_WxdT_hi [(size_t)DI * DI];   // Wxd transposed
__device__ __align__(16) bf16 g_WxdT_lo [(size_t)DI * DI];
__device__ __align__(16) bf16 g_Wcomb_hi[(size_t)DI * DI];   // Wdt @ Wxd
__device__ __align__(16) bf16 g_Wcomb_lo[(size_t)DI * DI];
__device__ __align__(16) bf16 g_xc_hi   [(size_t)MTOT * DI];
__device__ __align__(16) bf16 g_xc_lo   [(size_t)MTOT * DI];
__device__ __align__(16) bf16 g_yg_hi   [(size_t)MTOT * DI];
__device__ __align__(16) bf16 g_yg_lo   [(size_t)MTOT * DI];

// ======================= helpers ===========================================
__device__ __forceinline__ uint32_t smem_u32(const void* p) {
    uint32_t a;
    asm("{ .reg .u64 t; cvta.to.shared.u64 t, %1; cvt.u32.u64 %0, t; }"
        : "=r"(a) : "l"(p));
    return a;
}

__device__ __forceinline__ uint32_t swz(uint32_t off) {     // SW128 swizzle
    return off ^ ((off >> 3) & 0x70);
}

__device__ __forceinline__ void ldsm4(uint32_t* r, uint32_t addr) {
    asm volatile("ldmatrix.sync.aligned.m8n8.x4.shared.b16 {%0,%1,%2,%3}, [%4];"
        : "=r"(r[0]), "=r"(r[1]), "=r"(r[2]), "=r"(r[3]) : "r"(addr));
}

__device__ __forceinline__ void mma16816(float* c, const uint32_t* a,
                                         const uint32_t* b) {
    asm volatile(
        "mma.sync.aligned.m16n8k16.row.col.f32.bf16.bf16.f32 "
        "{%0,%1,%2,%3}, {%4,%5,%6,%7}, {%8,%9}, {%0,%1,%2,%3};"
        : "+f"(c[0]), "+f"(c[1]), "+f"(c[2]), "+f"(c[3])
        : "r"(a[0]), "r"(a[1]), "r"(a[2]), "r"(a[3]),
          "r"(b[0]), "r"(b[1]));
}

__device__ __forceinline__ void cp16(uint32_t dst, const void* src, uint32_t sz) {
    asm volatile("cp.async.cg.shared.global [%0], [%1], 16, %2;"
        :: "r"(dst), "l"(src), "r"(sz) : "memory");
}
#define CP_COMMIT() asm volatile("cp.async.commit_group;" ::: "memory")
#define CP_WAIT2()  asm volatile("cp.async.wait_group 2;" ::: "memory")

__device__ __forceinline__ void split2(float a, float b, bf162& h, bf162& l) {
    bf16 h0 = __float2bfloat16(a);
    bf16 h1 = __float2bfloat16(b);
    h.x = h0; h.y = h1;
    l.x = __float2bfloat16(a - __bfloat162float(h0));
    l.y = __float2bfloat16(b - __bfloat162float(h1));
}

__device__ __forceinline__ float softplus_fast(float v) {
    return (v > 20.f) ? v : log1pf(__expf(v));
}

// ---------------------------------------------------------------------------
// preprocessing: transpose Wxd (first NTRANS blocks) + split of x/Win/Wdt/Wout
// ---------------------------------------------------------------------------
__device__ __forceinline__ void split_body(const float* __restrict__ src,
                                           bf16* __restrict__ hi,
                                           bf16* __restrict__ lo, int i)
{
    float4 v = ((const float4*)src)[i];
    bf162 h0, h1, l0, l1;
    split2(v.x, v.y, h0, l0);
    split2(v.z, v.w, h1, l1);
    ((bf162*)hi)[i*2]   = h0;  ((bf162*)hi)[i*2+1] = h1;
    ((bf162*)lo)[i*2]   = l0;  ((bf162*)lo)[i*2+1] = l1;
}

#define NTRANS 4096   // (DI/32)^2 transpose blocks

__global__ void preproc_kernel(
    const float* __restrict__ Wx, bf16* __restrict__ Thi, bf16* __restrict__ Tlo,
    const float* __restrict__ s0, bf16* __restrict__ h0, bf16* __restrict__ l0, int n0,
    const float* __restrict__ s1, bf16* __restrict__ h1, bf16* __restrict__ l1, int n1,
    const float* __restrict__ s2, bf16* __restrict__ h2, bf16* __restrict__ l2, int n2,
    const float* __restrict__ s3, bf16* __restrict__ h3, bf16* __restrict__ l3, int n3)
{
    __shared__ float tile[32][33];
    const int blk = blockIdx.x;
    if (blk < NTRANS) {
        const int bx = (blk & 63) * 32;   // j block
        const int by = (blk >> 6) * 32;   // k block
        const int tx = threadIdx.x & 31;
        const int ty = threadIdx.x >> 5;
#pragma unroll
        for (int i = 0; i < 4; i++) {
            const int k = by + ty + i * 8;
            tile[ty + i * 8][tx] = Wx[(size_t)k * DI + bx + tx];
        }
        __syncthreads();
#pragma unroll
        for (int i = 0; i < 4; i++) {
            const int j = bx + ty + i * 8;
            const float v = tile[tx][ty + i * 8];
            bf16 h = __float2bfloat16(v);
            Thi[(size_t)j * DI + by + tx] = h;
            Tlo[(size_t)j * DI + by + tx] = __float2bfloat16(v - __bfloat162float(h));
        }
    } else {
        const int i = (blk - NTRANS) * 256 + threadIdx.x;
        if (i < n0)                      split_body(s0, h0, l0, i);
        else if (i < n0 + n1)            split_body(s1, h1, l1, i - n0);
        else if (i < n0 + n1 + n2)       split_body(s2, h2, l2, i - n0 - n1);
        else if (i < n0 + n1 + n2 + n3)  split_body(s3, h3, l3, i - n0 - n1 - n2);
    }
}

// ===========================================================================
// split-bf16 GEMM body:  C[M,N] = A[M,K] * W[N,K]^T  (bf16 hi/lo in)
// CTA: 128x128 tile, 8 warps (2x4), warp tile 64x32, K-chunk 64,
// 3-stage cp.async pipeline, R12-proven two-barrier ordering, term-outer MMAs.
// MODE 0: fp32. MODE 1: softplus+bias fp32. MODE 3: bf16 hi/lo out.
// ===========================================================================

#define TILE_B   16384            // 128 rows x 128 bytes (64 bf16)
#define STAGE_B  (4 * TILE_B)     // Ahi, Alo, Whi, Wlo
#define NSTG     3
#define GEMM_SMEM (NSTG * STAGE_B)   // 196608
#define GTHREADS 256

__device__ __forceinline__ void stage_load(
    uint32_t sbase,
    const bf16* __restrict__ Ahi, const bf16* __restrict__ Alo, int lda, int m0,
    const bf16* __restrict__ Whi, const bf16* __restrict__ Wlo, int ldw,
    int n0, int N, int k0, int tid)
{
#pragma unroll
    for (int it = 0; it < 4; it++) {
        const int chunk = tid + it * GTHREADS;  // 0..1023
        const int row = chunk >> 3;
        const int c16 = chunk & 7;
        const uint32_t soff = swz((uint32_t)(row * 128 + c16 * 16));
        const size_t aoff = (size_t)(m0 + row) * lda + k0 + c16 * 8;
        cp16(sbase + 0 * TILE_B + soff, Ahi + aoff, 16);
        cp16(sbase + 1 * TILE_B + soff, Alo + aoff, 16);
        const int nr = n0 + row;
        const bool v = nr < N;
        const size_t woff = (size_t)(v ? nr : 0) * ldw + k0 + c16 * 8;
        const uint32_t sz = v ? 16u : 0u;
        cp16(sbase + 2 * TILE_B + soff, Whi + woff, sz);
        cp16(sbase + 3 * TILE_B + soff, Wlo + woff, sz);
    }
}

template<int MODE>
__device__ __forceinline__ void gemm_body(
    const bf16* __restrict__ Ahi, const bf16* __restrict__ Alo, int lda,
    const bf16* __restrict__ Whi, const bf16* __restrict__ Wlo,
    const float* __restrict__ bias,
    float* __restrict__ C, int ldc,
    bf16* __restrict__ Chi, bf16* __restrict__ Clo,
    int M, int N, int K, int bx, int by)
{
    extern __shared__ __align__(1024) char smem[];
    const uint32_t sb  = smem_u32(smem);
    const int tid  = threadIdx.x;
    const int wid  = tid >> 5;
    const int lane = tid & 31;
    const int wm   = wid >> 2;       // 0..1  (m)
    const int wn   = wid & 3;        // 0..3  (n)
    const int m0   = by * 128;
    const int n0   = bx * 128;

    const int g     = lane >> 3;
    const int aRow  = (lane & 7) + ((g & 1) << 3);
    const int aKsg  = (g >> 1) << 3;
    const int bRow  = (lane & 7) + ((g >> 1) << 3);
    const int bKsg  = (g & 1) << 3;

    float Cf[4][4][4];
#pragma unroll
    for (int i = 0; i < 4; i++)
#pragma unroll
        for (int j = 0; j < 4; j++)
#pragma unroll
            for (int e = 0; e < 4; e++) Cf[i][j][e] = 0.f;

    const int NC = K >> 6;

#pragma unroll
    for (int p = 0; p < NSTG; p++) {
        if (p < NC)
            stage_load(sb + p * STAGE_B, Ahi, Alo, lda, m0,
                       Whi, Wlo, K, n0, N, p << 6, tid);
        CP_COMMIT();
    }

    for (int c = 0; c < NC; c++) {
        CP_WAIT2();
        __syncthreads();

        const uint32_t base = sb + (uint32_t)((c % NSTG) * STAGE_B);
        const uint32_t bAhi = base + 0 * TILE_B;
        const uint32_t bAlo = base + 1 * TILE_B;
        const uint32_t bWhi = base + 2 * TILE_B;
        const uint32_t bWlo = base + 3 * TILE_B;

#pragma unroll
        for (int ks = 0; ks < 4; ks++) {
            uint32_t ahi[4][4], alo[4][4], whi[2][4], wlo[2][4];
#pragma unroll
            for (int fm = 0; fm < 4; fm++) {
                uint32_t off = swz((uint32_t)((wm*64 + fm*16 + aRow) * 128
                                              + (ks*16 + aKsg) * 2));
                ldsm4(ahi[fm], bAhi + off);
                ldsm4(alo[fm], bAlo + off);
            }
#pragma unroll
            for (int h = 0; h < 2; h++) {
                uint32_t off = swz((uint32_t)((wn*32 + h*16 + bRow) * 128
                                              + (ks*16 + bKsg) * 2));
                ldsm4(whi[h], bWhi + off);
                ldsm4(wlo[h], bWlo + off);
            }
            // term-outer: 16 independent accumulators between same-acc reuse
#pragma unroll
            for (int t = 0; t < 3; t++) {
#pragma unroll
                for (int fm = 0; fm < 4; fm++) {
#pragma unroll
                    for (int fn = 0; fn < 4; fn++) {
                        const uint32_t* a = (t == 2) ? alo[fm] : ahi[fm];
                        const uint32_t* b = (t == 1)
                            ? &wlo[fn >> 1][(fn & 1) * 2]
                            : &whi[fn >> 1][(fn & 1) * 2];
                        mma16816(Cf[fm][fn], a, b);
                    }
                }
            }
        }
        __syncthreads();

        {
            const int cn = c + NSTG;
            if (cn < NC)
                stage_load(sb + (c % NSTG) * STAGE_B, Ahi, Alo, lda, m0,
                           Whi, Wlo, K, n0, N, cn << 6, tid);
            CP_COMMIT();
        }
    }

    // epilogue
    const int mrow = m0 + wm * 64 + (lane >> 2);
    const int ncol = n0 + wn * 32 + (lane & 3) * 2;
#pragma unroll
    for (int fm = 0; fm < 4; fm++) {
#pragma unroll
        for (int fn = 0; fn < 4; fn++) {
#pragma unroll
            for (int half = 0; half < 2; half++) {
                const int m = mrow + fm * 16 + half * 8;
                const int n = ncol + fn * 8;
                if (n < N) {
                    float v0 = Cf[fm][fn][half * 2 + 0];
                    float v1 = Cf[fm][fn][half * 2 + 1];
                    if (MODE == 1) {
                        v0 = softplus_fast(v0 + bias[n]);
                        v1 = softplus_fast(v1 + bias[n + 1]);
                    }
                    if (MODE == 3) {
                        bf162 h, l;
                        split2(v0, v1, h, l);
                        *(bf162*)&Chi[(size_t)m * ldc + n] = h;
                        *(bf162*)&Clo[(size_t)m * ldc + n] = l;
                    } else {
                        *(float2*)&C[(size_t)m * ldc + n] = make_float2(v0, v1);
                    }
                }
            }
        }
    }
}

template<int MODE>
__global__ void __launch_bounds__(GTHREADS, 1) hgemm_bf(
    const bf16* __restrict__ Ahi, const bf16* __restrict__ Alo, int lda,
    const bf16* __restrict__ Whi, const bf16* __restrict__ Wlo,
    const float* __restrict__ bias,
    float* __restrict__ C, int ldc,
    bf16* __restrict__ Chi, bf16* __restrict__ Clo,
    int M, int N, int K)
{
    gemm_body<MODE>(Ahi, Alo, lda, Whi, Wlo, bias, C, ldc, Chi, Clo,
                    M, N, K, blockIdx.x, blockIdx.y);
}

// fused launch: partition 0 = GEMM1 (MODE 0), partition 1 = Wcomb (MODE 3)
__global__ void __launch_bounds__(GTHREADS, 1) hgemm_dual(
    const bf16* __restrict__ A0hi, const bf16* __restrict__ A0lo, int lda0,
    const bf16* __restrict__ W0hi, const bf16* __restrict__ W0lo,
    float* __restrict__ C0, int ldc0, int M0, int N0, int K0, int gx0, int gy0,
    const bf16* __restrict__ A1hi, const bf16* __restrict__ A1lo, int lda1,
    const bf16* __restrict__ W1hi, const bf16* __restrict__ W1lo,
    bf16* __restrict__ C1hi, bf16* __restrict__ C1lo, int ldc1,
    int M1, int N1, int K1, int gx1)
{
    int id = blockIdx.x;
    if (id < gx0 * gy0) {
        gemm_body<0>(A0hi, A0lo, lda0, W0hi, W0lo, nullptr, C0, ldc0,
                     nullptr, nullptr, M0, N0, K0, id % gx0, id / gx0);
    } else {
        id -= gx0 * gy0;
        gemm_body<3>(A1hi, A1lo, lda1, W1hi, W1lo, nullptr, nullptr, ldc1,
                     C1hi, C1lo, M1, N1, K1, id % gx1, id / gx1);
    }
}

// ---------------------------------------------------------------------------
// bc body (partition of the delta launch): bc[m,n] = dot(xconv[m,:], Wx[DI+n,:])
// xconv reconstructed from hi+lo; BCROWS=16 rows per block (128KB smem window).
// ---------------------------------------------------------------------------
#define BCROWS 16
__device__ __forceinline__ void bc_body(
    const bf16* __restrict__ xchi, const bf16* __restrict__ xclo,
    const float* __restrict__ Wx, float* __restrict__ bc, int blk)
{
    extern __shared__ __align__(1024) char smem[];
    float (*rows)[DI] = (float(*)[DI])smem;    // 16 x 2048 x 4B = 128 KB
    const int m0 = blk * BCROWS;
    for (int i = threadIdx.x; i < BCROWS * DI; i += 256) {
        const int r = i >> 11, c = i & (DI - 1);
        const size_t idx = (size_t)(m0 + r) * DI + c;
        rows[r][c] = __bfloat162float(xchi[idx]) + __bfloat162float(xclo[idx]);
    }
    __syncthreads();

    const int w = threadIdx.x >> 5, lane = threadIdx.x & 31;
#pragma unroll
    for (int o = 0; o < 4; o++) {
        const int n = w * 4 + o;
        const float* wrow = Wx + (size_t)(DI + n) * DI;
        float acc[BCROWS];
#pragma unroll
        for (int r = 0; r < BCROWS; r++) acc[r] = 0.f;
        for (int k = lane; k < DI; k += 32) {
            const float wv = wrow[k];
#pragma unroll
            for (int r = 0; r < BCROWS; r++) acc[r] += rows[r][k] * wv;
        }
#pragma unroll
        for (int r = 0; r < BCROWS; r++) {
#pragma unroll
            for (int off = 16; off; off >>= 1)
                acc[r] += __shfl_xor_sync(0xFFFFFFFFu, acc[r], off);
            if (lane == 0) bc[(size_t)(m0 + r) * 32 + n] = acc[r];
        }
    }
}

// fused launch: partition 0 = delta GEMM (MODE 1), partition 1 = bc blocks
__global__ void __launch_bounds__(GTHREADS, 1) hgemm_delta_bc(
    const bf16* __restrict__ xchi, const bf16* __restrict__ xclo,
    const bf16* __restrict__ Wchi, const bf16* __restrict__ Wclo,
    const float* __restrict__ bias, float* __restrict__ delta,
    const float* __restrict__ Wx, float* __restrict__ bc,
    int gx0, int gy0)
{
    int id = blockIdx.x;
    if (id < gx0 * gy0) {
        gemm_body<1>(xchi, xclo, DI, Wchi, Wclo, bias, delta, DI,
                     nullptr, nullptr, MTOT, DI, DI, id % gx0, id / gx0);
    } else {
        bc_body(xchi, xclo, Wx, bc, id - gx0 * gy0);
    }
}

// ---------------------------------------------------------------------------
// Depthwise causal conv (K=4) + SiLU, sliding-window; writes bf16 hi/lo only.
// ---------------------------------------------------------------------------
__global__ void conv_silu_kernel(const float* __restrict__ xz,
                                 const float* __restrict__ w,
                                 const float* __restrict__ bconv,
                                 bf16* __restrict__ xchi,
                                 bf16* __restrict__ xclo)
{
    const int idx = blockIdx.x * blockDim.x + threadIdx.x;  // MTOT*DI/16 thr
    if (idx >= MTOT * DI / 16) return;
    const int ND4 = DI / 4;
    const int d4  = (idx & (ND4 - 1)) * 4;
    const int ml  = (idx / ND4) * 4;
    const int l   = ml & (SEQ - 1);

    float4 wt[4];
#pragma unroll
    for (int e = 0; e < 4; e++) wt[e] = ((const float4*)w)[d4 + e];
    const float4 bcv = *(const float4*)(bconv + d4);
    const float bias[4] = {bcv.x, bcv.y, bcv.z, bcv.w};

    float win[7][4];
#pragma unroll
    for (int j = 0; j < 7; j++) {
        const int lt = l - 3 + j;
        if (lt >= 0) {
            float4 v = *(const float4*)(xz + (size_t)(ml - 3 + j) * (2 * DI) + d4);
            win[j][0] = v.x; win[j][1] = v.y; win[j][2] = v.z; win[j][3] = v.w;
        } else {
            win[j][0] = win[j][1] = win[j][2] = win[j][3] = 0.f;
        }
    }

#pragma unroll
    for (int t = 0; t < 4; t++) {
        float o[4];
#pragma unroll
        for (int e = 0; e < 4; e++) {
            const float* wk = &wt[e].x;
            float acc = bias[e];
#pragma unroll
            for (int k = 0; k < 4; k++)
                acc += win[t + k][e] * wk[k];
            o[e] = acc / (1.f + __expf(-acc));
        }
        const size_t row = (size_t)(ml + t) * DI + d4;
        bf162 h0, h1, l0, l1;
        split2(o[0], o[1], h0, l0);
        split2(o[2], o[3], h1, l1);
        *(bf162*)(xchi + row)     = h0;  *(bf162*)(xchi + row + 2) = h1;
        *(bf162*)(xclo + row)     = l0;  *(bf162*)(xclo + row + 2) = l1;
    }
}

// ---------------------------------------------------------------------------
// Scan pass A  (xconv reconstructed from hi/lo; B cols from bc, stride 32)
// ---------------------------------------------------------------------------
__global__ void __launch_bounds__(256) scan_passA(
    const bf16* __restrict__ xchi, const bf16* __restrict__ xclo,
    const float* __restrict__ delta,
    const float* __restrict__ bc,    const float* __restrict__ A_log,
    float* __restrict__ chA, float* __restrict__ chH)
{
    __shared__ float Bsm[CHUNK][DS];
    const int d = blockIdx.x * blockDim.x + threadIdx.x;
    const int c = blockIdx.y, b = blockIdx.z;

    for (int i = threadIdx.x; i < CHUNK * DS; i += blockDim.x) {
        const int t = i >> 4, s = i & 15;
        Bsm[t][s] = bc[(size_t)(b * SEQ + c * CHUNK + t) * 32 + s];
    }
    __syncthreads();

    float Aa[DS], st[DS], cum[DS];
#pragma unroll
    for (int s = 0; s < DS; s++) {
        Aa[s]  = -expf(A_log[d * DS + s]);
        st[s]  = 0.f;
        cum[s] = 1.f;
    }
    const size_t base = (size_t)(b * SEQ + c * CHUNK) * DI + d;
    for (int t = 0; t < CHUNK; t++) {
        const float dt = delta[base + (size_t)t * DI];
        const float xv = __bfloat162float(xchi[base + (size_t)t * DI])
                       + __bfloat162float(xclo[base + (size_t)t * DI]);
#pragma unroll
        for (int s = 0; s < DS; s++) {
            const float dec = __expf(dt * Aa[s]);
            cum[s] *= dec;
            st[s]   = dec * st[s] + Bsm[t][s] * xv;
        }
    }
    const size_t o = ((size_t)(b * NCH + c) * DI + d) * DS;
#pragma unroll
    for (int s = 0; s < DS; s++) { chA[o + s] = cum[s]; chH[o + s] = st[s]; }
}

// ---------------------------------------------------------------------------
// Scan pass B
// ---------------------------------------------------------------------------
__global__ void scan_passB(const float* __restrict__ chA,
                           const float* __restrict__ chH,
                           float* __restrict__ hInit)
{
    const int idx = blockIdx.x * blockDim.x + threadIdx.x;
    if (idx >= BATCH * DI) return;
    const int b = idx / DI, d = idx % DI;
    float h[DS];
#pragma unroll
    for (int s = 0; s < DS; s++) h[s] = 0.f;
    for (int c = 0; c < NCH; c++) {
        const size_t o = ((size_t)(b * NCH + c) * DI + d) * DS;
#pragma unroll
        for (int s = 0; s < DS; s++) hInit[o + s] = h[s];
#pragma unroll
        for (int s = 0; s < DS; s++) h[s] = chA[o + s] * h[s] + chH[o + s];
    }
}

// ---------------------------------------------------------------------------
// Scan pass C: replay + C-contraction + D-skip + y*silu(z); writes yg hi/lo.
// ---------------------------------------------------------------------------
__global__ void __launch_bounds__(256) scan_passC(
    const bf16* __restrict__ xchi, const bf16* __restrict__ xclo,
    const float* __restrict__ delta,
    const float* __restrict__ bc,    const float* __restrict__ A_log,
    const float* __restrict__ Dv,    const float* __restrict__ xz,
    const float* __restrict__ hInit,
    bf16* __restrict__ yghi, bf16* __restrict__ yglo)
{
    __shared__ float Bsm[CHUNK][DS];
    __shared__ float Csm[CHUNK][DS];
    const int d = blockIdx.x * blockDim.x + threadIdx.x;
    const int c = blockIdx.y, b = blockIdx.z;

    for (int i = threadIdx.x; i < CHUNK * DS; i += blockDim.x) {
        const int t = i >> 4, s = i & 15;
        const size_t row = (size_t)(b * SEQ + c * CHUNK + t) * 32;
        Bsm[t][s] = bc[row + s];
        Csm[t][s] = bc[row + 16 + s];
    }
    __syncthreads();

    float Aa[DS], st[DS];
    const size_t o = ((size_t)(b * NCH + c) * DI + d) * DS;
#pragma unroll
    for (int s = 0; s < DS; s++) {
        Aa[s] = -expf(A_log[d * DS + s]);
        st[s] = hInit[o + s];
    }
    const float Dd = Dv[d];
    const size_t base = (size_t)(b * SEQ + c * CHUNK) * DI + d;
    for (int t = 0; t < CHUNK; t++) {
        const float dt = delta[base + (size_t)t * DI];
        const float xv = __bfloat162float(xchi[base + (size_t)t * DI])
                       + __bfloat162float(xclo[base + (size_t)t * DI]);
        float y = 0.f;
#pragma unroll
        for (int s = 0; s < DS; s++) {
            const float dec = __expf(dt * Aa[s]);
            st[s] = dec * st[s] + Bsm[t][s] * xv;
            y += st[s] * Csm[t][s];
        }
        y += Dd * xv;
        const float z = xz[(size_t)(b * SEQ + c * CHUNK + t) * (2 * DI) + DI + d];
        const float sg = 1.f / (1.f + __expf(-z));
        const float v = y * (z * sg);
        const size_t oi = base + (size_t)t * DI;
        bf16 h = __float2bfloat16(v);
        yghi[oi] = h;
        yglo[oi] = __float2bfloat16(v - __bfloat162float(h));
    }
}

// ---------------------------------------------------------------------------
template<int MODE>
static void launch_hgemm(const bf16* Ahi, const bf16* Alo, int lda,
                         const bf16* Whi, const bf16* Wlo,
                         const float* bias, float* C, int ldc,
                         bf16* Chi, bf16* Clo, int M, int N, int K)
{
    dim3 grid((N + 127) / 128, M / 128);
    cudaFuncSetAttribute(hgemm_bf<MODE>,
        cudaFuncAttributeMaxDynamicSharedMemorySize, GEMM_SMEM);
    hgemm_bf<MODE><<<grid, GTHREADS, GEMM_SMEM>>>(Ahi, Alo, lda, Whi, Wlo,
                                                  bias, C, ldc, Chi, Clo, M, N, K);
}

extern "C" void kernel_launch(void* const* d_in, const int* in_sizes, int n_in,
                              void* d_out, int out_size)
{
    const float* x      = (const float*)d_in[0];
    const float* W_in   = (const float*)d_in[1];
    const float* w_conv = (const float*)d_in[2];
    const float* b_conv = (const float*)d_in[3];
    const float* W_x    = (const float*)d_in[4];
    const float* W_dt   = (const float*)d_in[5];
    const float* b_dt   = (const float*)d_in[6];
    const float* A_log  = (const float*)d_in[7];
    const float* Dv     = (const float*)d_in[8];
    const float* W_out  = (const float*)d_in[9];
    float* out = (float*)d_out;

    float *xz, *delta, *bc, *chA, *chH, *hInit;
    cudaGetSymbolAddress((void**)&xz,    g_xz);
    cudaGetSymbolAddress((void**)&delta, g_delta);
    cudaGetSymbolAddress((void**)&bc,    g_bc);
    cudaGetSymbolAddress((void**)&chA,   g_chA);
    cudaGetSymbolAddress((void**)&chH,   g_chH);
    cudaGetSymbolAddress((void**)&hInit, g_hInit);

    bf16 *x_hi, *x_lo, *Win_hi, *Win_lo, *Wdt_hi, *Wdt_lo, *Wout_hi, *Wout_lo,
         *WxdT_hi, *WxdT_lo, *Wcomb_hi, *Wcomb_lo, *xc_hi, *xc_lo, *yg_hi, *yg_lo;
    cudaGetSymbolAddress((void**)&x_hi,     g_x_hi);
    cudaGetSymbolAddress((void**)&x_lo,     g_x_lo);
    cudaGetSymbolAddress((void**)&Win_hi,   g_Win_hi);
    cudaGetSymbolAddress((void**)&Win_lo,   g_Win_lo);
    cudaGetSymbolAddress((void**)&Wdt_hi,   g_Wdt_hi);
    cudaGetSymbolAddress((void**)&Wdt_lo,   g_Wdt_lo);
    cudaGetSymbolAddress((void**)&Wout_hi,  g_Wout_hi);
    cudaGetSymbolAddress((void**)&Wout_lo,  g_Wout_lo);
    cudaGetSymbolAddress((void**)&WxdT_hi,  g_WxdT_hi);
    cudaGetSymbolAddress((void**)&WxdT_lo,  g_WxdT_lo);
    cudaGetSymbolAddress((void**)&Wcomb_hi, g_Wcomb_hi);
    cudaGetSymbolAddress((void**)&Wcomb_lo, g_Wcomb_lo);
    cudaGetSymbolAddress((void**)&xc_hi,    g_xc_hi);
    cudaGetSymbolAddress((void**)&xc_lo,    g_xc_lo);
    cudaGetSymbolAddress((void**)&yg_hi,    g_yg_hi);
    cudaGetSymbolAddress((void**)&yg_lo,    g_yg_lo);

    // [0] preprocessing: transpose Wxd + split of x, W_in, W_dt, W_out
    {
        int n0 = MTOT * DM / 4;
        int n1 = (2 * DI) * DM / 4;
        int n2 = DI * DI / 4;
        int n3 = DM * DI / 4;
        int tot = n0 + n1 + n2 + n3;
        int blocks = NTRANS + (tot + 255) / 256;
        preproc_kernel<<<blocks, 256>>>(
            W_x, WxdT_hi, WxdT_lo,
            x, x_hi, x_lo, n0,
            W_in, Win_hi, Win_lo, n1,
            W_dt, Wdt_hi, Wdt_lo, n2,
            W_out, Wout_hi, Wout_lo, n3);
    }
    // [1] fused: GEMM1 (xz = x @ W_in^T) + Wcomb = Wdt @ Wxd
    {
        const int gx0 = (2 * DI) / 128, gy0 = MTOT / 128;   // 32 x 32
        const int gx1 = DI / 128;                            // 16 (gy1 = 16)
        const int total = gx0 * gy0 + gx1 * (DI / 128);
        cudaFuncSetAttribute(hgemm_dual,
            cudaFuncAttributeMaxDynamicSharedMemorySize, GEMM_SMEM);
        hgemm_dual<<<total, GTHREADS, GEMM_SMEM>>>(
            x_hi, x_lo, DM, Win_hi, Win_lo, xz, 2 * DI, MTOT, 2 * DI, DM, gx0, gy0,
            Wdt_hi, Wdt_lo, DI, WxdT_hi, WxdT_lo, Wcomb_hi, Wcomb_lo, DI,
            DI, DI, DI, gx1);
    }
    // [2] depthwise causal conv + silu (sliding window, hi/lo only)
    {
        int n = MTOT * DI / 16;
        conv_silu_kernel<<<(n + 255) / 256, 256>>>(xz, w_conv, b_conv,
                                                   xc_hi, xc_lo);
    }
    // [3] fused: delta = softplus(xconv @ Wcomb^T + b_dt)  +  bc columns
    {
        const int gx0 = DI / 128, gy0 = MTOT / 128;          // 16 x 32 = 512
        const int total = gx0 * gy0 + MTOT / BCROWS;         // + 256 bc blocks
        cudaFuncSetAttribute(hgemm_delta_bc,
            cudaFuncAttributeMaxDynamicSharedMemorySize, GEMM_SMEM);
        hgemm_delta_bc<<<total, GTHREADS, GEMM_SMEM>>>(
            xc_hi, xc_lo, Wcomb_hi, Wcomb_lo, b_dt, delta, W_x, bc, gx0, gy0);
    }
    // [4-6] chunked selective scan
    {
        dim3 gridA(DI / 256, NCH, BATCH);
        scan_passA<<<gridA, 256>>>(xc_hi, xc_lo, delta, bc, A_log, chA, chH);
        scan_passB<<<(BATCH * DI + 255) / 256, 256>>>(chA, chH, hInit);
        scan_passC<<<gridA, 256>>>(xc_hi, xc_lo, delta, bc, A_log, Dv, xz,
                                   hInit, yg_hi, yg_lo);
    }
    // [7] out = yg @ W_out^T
    launch_hgemm<0>(yg_hi, yg_lo, DI, Wout_hi, Wout_lo, nullptr,
                    out, DM, nullptr, nullptr, MTOT, DM, DI);
}

// round 17
// speedup vs baseline: 1.0016x; 1.0016x over previous
#include <cuda_runtime.h>
#include <cuda_bf16.h>
#include <cstdint>
#include <math.h>

// ---------------------------------------------------------------------------
// SelectiveSSM (Mamba-style block) — split-bf16 HMMA GEMMs, cp.async pipeline
//   B=2, L=2048, d_model=1024, d_inner=2048, d_state=16, d_conv=4
// R15: R14 + bc fused into delta-GEMM launch (tail fill), fp32 xconv dropped
// (consumers reconstruct hi+lo), transpose merged into preproc, __expf paths.
// ---------------------------------------------------------------------------

#define BATCH  2
#define SEQ    2048
#define DM     1024
#define DI     2048
#define DS     16
#define DC     4
#define CHUNK  128
#define NCH    (SEQ / CHUNK)    // 16
#define MTOT   (BATCH * SEQ)    // 4096

typedef __nv_bfloat16  bf16;
typedef __nv_bfloat162 bf162;

// ------------------------- scratch (static, no mallocs) -------------------
__device__ float g_xz   [(size_t)MTOT * 2 * DI];
__device__ float g_delta[(size_t)MTOT * DI];
__device__ float g_bc   [(size_t)MTOT * 2 * DS];          // B,C cols (fp32)
__device__ float g_chA  [(size_t)BATCH * NCH * DI * DS];
__device__ float g_chH  [(size_t)BATCH * NCH * DI * DS];
__device__ float g_hInit[(size_t)BATCH * NCH * DI * DS];

// bf16 hi/lo operand buffers
__device__ __align__(16) bf16 g_x_hi    [(size_t)MTOT * DM];
__device__ __align__(16) bf16 g_x_lo    [(size_t)MTOT * DM];
__device__ __align__(16) bf16 g_Win_hi  [(size_t)(2*DI) * DM];
__device__ __align__(16) bf16 g_Win_lo  [(size_t)(2*DI) * DM];
__device__ __align__(16) bf16 g_Wdt_hi  [(size_t)DI * DI];
__device__ __align__(16) bf16 g_Wdt_lo  [(size_t)DI * DI];
__device__ __align__(16) bf16 g_Wout_hi [(size_t)DM * DI];
__device__ __align__(16) bf16 g_Wout_lo [(size_t)DM * DI];
__device__ __align__(16) bf16 g_WxdT_hi [(size_t)DI * DI];   // Wxd transposed
__device__ __align__(16) bf16 g_WxdT_lo [(size_t)DI * DI];
__device__ __align__(16) bf16 g_Wcomb_hi[(size_t)DI * DI];   // Wdt @ Wxd
__device__ __align__(16) bf16 g_Wcomb_lo[(size_t)DI * DI];
__device__ __align__(16) bf16 g_xc_hi   [(size_t)MTOT * DI];
__device__ __align__(16) bf16 g_xc_lo   [(size_t)MTOT * DI];
__device__ __align__(16) bf16 g_yg_hi   [(size_t)MTOT * DI];
__device__ __align__(16) bf16 g_yg_lo   [(size_t)MTOT * DI];

// ======================= helpers ===========================================
__device__ __forceinline__ uint32_t smem_u32(const void* p) {
    uint32_t a;
    asm("{ .reg .u64 t; cvta.to.shared.u64 t, %1; cvt.u32.u64 %0, t; }"
        : "=r"(a) : "l"(p));
    return a;
}

__device__ __forceinline__ uint32_t swz(uint32_t off) {     // SW128 swizzle
    return off ^ ((off >> 3) & 0x70);
}

__device__ __forceinline__ void ldsm4(uint32_t* r, uint32_t addr) {
    asm volatile("ldmatrix.sync.aligned.m8n8.x4.shared.b16 {%0,%1,%2,%3}, [%4];"
        : "=r"(r[0]), "=r"(r[1]), "=r"(r[2]), "=r"(r[3]) : "r"(addr));
}

__device__ __forceinline__ void mma16816(float* c, const uint32_t* a,
                                         const uint32_t* b) {
    asm volatile(
        "mma.sync.aligned.m16n8k16.row.col.f32.bf16.bf16.f32 "
        "{%0,%1,%2,%3}, {%4,%5,%6,%7}, {%8,%9}, {%0,%1,%2,%3};"
        : "+f"(c[0]), "+f"(c[1]), "+f"(c[2]), "+f"(c[3])
        : "r"(a[0]), "r"(a[1]), "r"(a[2]), "r"(a[3]),
          "r"(b[0]), "r"(b[1]));
}

__device__ __forceinline__ void cp16(uint32_t dst, const void* src, uint32_t sz) {
    asm volatile("cp.async.cg.shared.global [%0], [%1], 16, %2;"
        :: "r"(dst), "l"(src), "r"(sz) : "memory");
}
#define CP_COMMIT() asm volatile("cp.async.commit_group;" ::: "memory")
#define CP_WAIT2()  asm volatile("cp.async.wait_group 2;" ::: "memory")

__device__ __forceinline__ void split2(float a, float b, bf162& h, bf162& l) {
    bf16 h0 = __float2bfloat16(a);
    bf16 h1 = __float2bfloat16(b);
    h.x = h0; h.y = h1;
    l.x = __float2bfloat16(a - __bfloat162float(h0));
    l.y = __float2bfloat16(b - __bfloat162float(h1));
}

__device__ __forceinline__ float softplus_fast(float v) {
    return (v > 20.f) ? v : log1pf(__expf(v));
}

// ---------------------------------------------------------------------------
// preprocessing: transpose Wxd (first NTRANS blocks) + split of x/Win/Wdt/Wout
// ---------------------------------------------------------------------------
__device__ __forceinline__ void split_body(const float* __restrict__ src,
                                           bf16* __restrict__ hi,
                                           bf16* __restrict__ lo, int i)
{
    float4 v = ((const float4*)src)[i];
    bf162 h0, h1, l0, l1;
    split2(v.x, v.y, h0, l0);
    split2(v.z, v.w, h1, l1);
    ((bf162*)hi)[i*2]   = h0;  ((bf162*)hi)[i*2+1] = h1;
    ((bf162*)lo)[i*2]   = l0;  ((bf162*)lo)[i*2+1] = l1;
}

#define NTRANS 4096   // (DI/32)^2 transpose blocks

__global__ void preproc_kernel(
    const float* __restrict__ Wx, bf16* __restrict__ Thi, bf16* __restrict__ Tlo,
    const float* __restrict__ s0, bf16* __restrict__ h0, bf16* __restrict__ l0, int n0,
    const float* __restrict__ s1, bf16* __restrict__ h1, bf16* __restrict__ l1, int n1,
    const float* __restrict__ s2, bf16* __restrict__ h2, bf16* __restrict__ l2, int n2,
    const float* __restrict__ s3, bf16* __restrict__ h3, bf16* __restrict__ l3, int n3)
{
    __shared__ float tile[32][33];
    const int blk = blockIdx.x;
    if (blk < NTRANS) {
        const int bx = (blk & 63) * 32;   // j block
        const int by = (blk >> 6) * 32;   // k block
        const int tx = threadIdx.x & 31;
        const int ty = threadIdx.x >> 5;
#pragma unroll
        for (int i = 0; i < 4; i++) {
            const int k = by + ty + i * 8;
            tile[ty + i * 8][tx] = Wx[(size_t)k * DI + bx + tx];
        }
        __syncthreads();
#pragma unroll
        for (int i = 0; i < 4; i++) {
            const int j = bx + ty + i * 8;
            const float v = tile[tx][ty + i * 8];
            bf16 h = __float2bfloat16(v);
            Thi[(size_t)j * DI + by + tx] = h;
            Tlo[(size_t)j * DI + by + tx] = __float2bfloat16(v - __bfloat162float(h));
        }
    } else {
        const int i = (blk - NTRANS) * 256 + threadIdx.x;
        if (i < n0)                      split_body(s0, h0, l0, i);
        else if (i < n0 + n1)            split_body(s1, h1, l1, i - n0);
        else if (i < n0 + n1 + n2)       split_body(s2, h2, l2, i - n0 - n1);
        else if (i < n0 + n1 + n2 + n3)  split_body(s3, h3, l3, i - n0 - n1 - n2);
    }
}

// ===========================================================================
// split-bf16 GEMM body:  C[M,N] = A[M,K] * W[N,K]^T  (bf16 hi/lo in)
// CTA: 128x128 tile, 8 warps (2x4), warp tile 64x32, K-chunk 64,
// 3-stage cp.async pipeline, R12-proven two-barrier ordering, term-outer MMAs.
// MODE 0: fp32. MODE 1: softplus+bias fp32. MODE 3: bf16 hi/lo out.
// ===========================================================================

#define TILE_B   16384            // 128 rows x 128 bytes (64 bf16)
#define STAGE_B  (4 * TILE_B)     // Ahi, Alo, Whi, Wlo
#define NSTG     3
#define GEMM_SMEM (NSTG * STAGE_B)   // 196608
#define GTHREADS 256

__device__ __forceinline__ void stage_load(
    uint32_t sbase,
    const bf16* __restrict__ Ahi, const bf16* __restrict__ Alo, int lda, int m0,
    const bf16* __restrict__ Whi, const bf16* __restrict__ Wlo, int ldw,
    int n0, int N, int k0, int tid)
{
#pragma unroll
    for (int it = 0; it < 4; it++) {
        const int chunk = tid + it * GTHREADS;  // 0..1023
        const int row = chunk >> 3;
        const int c16 = chunk & 7;
        const uint32_t soff = swz((uint32_t)(row * 128 + c16 * 16));
        const size_t aoff = (size_t)(m0 + row) * lda + k0 + c16 * 8;
        cp16(sbase + 0 * TILE_B + soff, Ahi + aoff, 16);
        cp16(sbase + 1 * TILE_B + soff, Alo + aoff, 16);
        const int nr = n0 + row;
        const bool v = nr < N;
        const size_t woff = (size_t)(v ? nr : 0) * ldw + k0 + c16 * 8;
        const uint32_t sz = v ? 16u : 0u;
        cp16(sbase + 2 * TILE_B + soff, Whi + woff, sz);
        cp16(sbase + 3 * TILE_B + soff, Wlo + woff, sz);
    }
}

template<int MODE>
__device__ __forceinline__ void gemm_body(
    const bf16* __restrict__ Ahi, const bf16* __restrict__ Alo, int lda,
    const bf16* __restrict__ Whi, const bf16* __restrict__ Wlo,
    const float* __restrict__ bias,
    float* __restrict__ C, int ldc,
    bf16* __restrict__ Chi, bf16* __restrict__ Clo,
    int M, int N, int K, int bx, int by)
{
    extern __shared__ __align__(1024) char smem[];
    const uint32_t sb  = smem_u32(smem);
    const int tid  = threadIdx.x;
    const int wid  = tid >> 5;
    const int lane = tid & 31;
    const int wm   = wid >> 2;       // 0..1  (m)
    const int wn   = wid & 3;        // 0..3  (n)
    const int m0   = by * 128;
    const int n0   = bx * 128;

    const int g     = lane >> 3;
    const int aRow  = (lane & 7) + ((g & 1) << 3);
    const int aKsg  = (g >> 1) << 3;
    const int bRow  = (lane & 7) + ((g >> 1) << 3);
    const int bKsg  = (g & 1) << 3;

    float Cf[4][4][4];
#pragma unroll
    for (int i = 0; i < 4; i++)
#pragma unroll
        for (int j = 0; j < 4; j++)
#pragma unroll
            for (int e = 0; e < 4; e++) Cf[i][j][e] = 0.f;

    const int NC = K >> 6;

#pragma unroll
    for (int p = 0; p < NSTG; p++) {
        if (p < NC)
            stage_load(sb + p * STAGE_B, Ahi, Alo, lda, m0,
                       Whi, Wlo, K, n0, N, p << 6, tid);
        CP_COMMIT();
    }

    for (int c = 0; c < NC; c++) {
        CP_WAIT2();
        __syncthreads();

        const uint32_t base = sb + (uint32_t)((c % NSTG) * STAGE_B);
        const uint32_t bAhi = base + 0 * TILE_B;
        const uint32_t bAlo = base + 1 * TILE_B;
        const uint32_t bWhi = base + 2 * TILE_B;
        const uint32_t bWlo = base + 3 * TILE_B;

#pragma unroll
        for (int ks = 0; ks < 4; ks++) {
            uint32_t ahi[4][4], alo[4][4], whi[2][4], wlo[2][4];
#pragma unroll
            for (int fm = 0; fm < 4; fm++) {
                uint32_t off = swz((uint32_t)((wm*64 + fm*16 + aRow) * 128
                                              + (ks*16 + aKsg) * 2));
                ldsm4(ahi[fm], bAhi + off);
                ldsm4(alo[fm], bAlo + off);
            }
#pragma unroll
            for (int h = 0; h < 2; h++) {
                uint32_t off = swz((uint32_t)((wn*32 + h*16 + bRow) * 128
                                              + (ks*16 + bKsg) * 2));
                ldsm4(whi[h], bWhi + off);
                ldsm4(wlo[h], bWlo + off);
            }
            // term-outer: 16 independent accumulators between same-acc reuse
#pragma unroll
            for (int t = 0; t < 3; t++) {
#pragma unroll
                for (int fm = 0; fm < 4; fm++) {
#pragma unroll
                    for (int fn = 0; fn < 4; fn++) {
                        const uint32_t* a = (t == 2) ? alo[fm] : ahi[fm];
                        const uint32_t* b = (t == 1)
                            ? &wlo[fn >> 1][(fn & 1) * 2]
                            : &whi[fn >> 1][(fn & 1) * 2];
                        mma16816(Cf[fm][fn], a, b);
                    }
                }
            }
        }
        __syncthreads();

        {
            const int cn = c + NSTG;
            if (cn < NC)
                stage_load(sb + (c % NSTG) * STAGE_B, Ahi, Alo, lda, m0,
                           Whi, Wlo, K, n0, N, cn << 6, tid);
            CP_COMMIT();
        }
    }

    // epilogue
    const int mrow = m0 + wm * 64 + (lane >> 2);
    const int ncol = n0 + wn * 32 + (lane & 3) * 2;
#pragma unroll
    for (int fm = 0; fm < 4; fm++) {
#pragma unroll
        for (int fn = 0; fn < 4; fn++) {
#pragma unroll
            for (int half = 0; half < 2; half++) {
                const int m = mrow + fm * 16 + half * 8;
                const int n = ncol + fn * 8;
                if (n < N) {
                    float v0 = Cf[fm][fn][half * 2 + 0];
                    float v1 = Cf[fm][fn][half * 2 + 1];
                    if (MODE == 1) {
                        v0 = softplus_fast(v0 + bias[n]);
                        v1 = softplus_fast(v1 + bias[n + 1]);
                    }
                    if (MODE == 3) {
                        bf162 h, l;
                        split2(v0, v1, h, l);
                        *(bf162*)&Chi[(size_t)m * ldc + n] = h;
                        *(bf162*)&Clo[(size_t)m * ldc + n] = l;
                    } else {
                        *(float2*)&C[(size_t)m * ldc + n] = make_float2(v0, v1);
                    }
                }
            }
        }
    }
}

template<int MODE>
__global__ void __launch_bounds__(GTHREADS, 1) hgemm_bf(
    const bf16* __restrict__ Ahi, const bf16* __restrict__ Alo, int lda,
    const bf16* __restrict__ Whi, const bf16* __restrict__ Wlo,
    const float* __restrict__ bias,
    float* __restrict__ C, int ldc,
    bf16* __restrict__ Chi, bf16* __restrict__ Clo,
    int M, int N, int K)
{
    gemm_body<MODE>(Ahi, Alo, lda, Whi, Wlo, bias, C, ldc, Chi, Clo,
                    M, N, K, blockIdx.x, blockIdx.y);
}

// fused launch: partition 0 = GEMM1 (MODE 0), partition 1 = Wcomb (MODE 3)
__global__ void __launch_bounds__(GTHREADS, 1) hgemm_dual(
    const bf16* __restrict__ A0hi, const bf16* __restrict__ A0lo, int lda0,
    const bf16* __restrict__ W0hi, const bf16* __restrict__ W0lo,
    float* __restrict__ C0, int ldc0, int M0, int N0, int K0, int gx0, int gy0,
    const bf16* __restrict__ A1hi, const bf16* __restrict__ A1lo, int lda1,
    const bf16* __restrict__ W1hi, const bf16* __restrict__ W1lo,
    bf16* __restrict__ C1hi, bf16* __restrict__ C1lo, int ldc1,
    int M1, int N1, int K1, int gx1)
{
    int id = blockIdx.x;
    if (id < gx0 * gy0) {
        gemm_body<0>(A0hi, A0lo, lda0, W0hi, W0lo, nullptr, C0, ldc0,
                     nullptr, nullptr, M0, N0, K0, id % gx0, id / gx0);
    } else {
        id -= gx0 * gy0;
        gemm_body<3>(A1hi, A1lo, lda1, W1hi, W1lo, nullptr, nullptr, ldc1,
                     C1hi, C1lo, M1, N1, K1, id % gx1, id / gx1);
    }
}

// ---------------------------------------------------------------------------
// bc body (partition of the delta launch): bc[m,n] = dot(xconv[m,:], Wx[DI+n,:])
// xconv reconstructed from hi+lo; BCROWS=16 rows per block (128KB smem window).
// ---------------------------------------------------------------------------
#define BCROWS 16
__device__ __forceinline__ void bc_body(
    const bf16* __restrict__ xchi, const bf16* __restrict__ xclo,
    const float* __restrict__ Wx, float* __restrict__ bc, int blk)
{
    extern __shared__ __align__(1024) char smem[];
    float (*rows)[DI] = (float(*)[DI])smem;    // 16 x 2048 x 4B = 128 KB
    const int m0 = blk * BCROWS;
    for (int i = threadIdx.x; i < BCROWS * DI; i += 256) {
        const int r = i >> 11, c = i & (DI - 1);
        const size_t idx = (size_t)(m0 + r) * DI + c;
        rows[r][c] = __bfloat162float(xchi[idx]) + __bfloat162float(xclo[idx]);
    }
    __syncthreads();

    const int w = threadIdx.x >> 5, lane = threadIdx.x & 31;
#pragma unroll
    for (int o = 0; o < 4; o++) {
        const int n = w * 4 + o;
        const float* wrow = Wx + (size_t)(DI + n) * DI;
        float acc[BCROWS];
#pragma unroll
        for (int r = 0; r < BCROWS; r++) acc[r] = 0.f;
        for (int k = lane; k < DI; k += 32) {
            const float wv = wrow[k];
#pragma unroll
            for (int r = 0; r < BCROWS; r++) acc[r] += rows[r][k] * wv;
        }
#pragma unroll
        for (int r = 0; r < BCROWS; r++) {
#pragma unroll
            for (int off = 16; off; off >>= 1)
                acc[r] += __shfl_xor_sync(0xFFFFFFFFu, acc[r], off);
            if (lane == 0) bc[(size_t)(m0 + r) * 32 + n] = acc[r];
        }
    }
}

// fused launch: partition 0 = delta GEMM (MODE 1), partition 1 = bc blocks
__global__ void __launch_bounds__(GTHREADS, 1) hgemm_delta_bc(
    const bf16* __restrict__ xchi, const bf16* __restrict__ xclo,
    const bf16* __restrict__ Wchi, const bf16* __restrict__ Wclo,
    const float* __restrict__ bias, float* __restrict__ delta,
    const float* __restrict__ Wx, float* __restrict__ bc,
    int gx0, int gy0)
{
    int id = blockIdx.x;
    if (id < gx0 * gy0) {
        gemm_body<1>(xchi, xclo, DI, Wchi, Wclo, bias, delta, DI,
                     nullptr, nullptr, MTOT, DI, DI, id % gx0, id / gx0);
    } else {
        bc_body(xchi, xclo, Wx, bc, id - gx0 * gy0);
    }
}

// ---------------------------------------------------------------------------
// Depthwise causal conv (K=4) + SiLU, sliding-window; writes bf16 hi/lo only.
// ---------------------------------------------------------------------------
__global__ void conv_silu_kernel(const float* __restrict__ xz,
                                 const float* __restrict__ w,
                                 const float* __restrict__ bconv,
                                 bf16* __restrict__ xchi,
                                 bf16* __restrict__ xclo)
{
    const int idx = blockIdx.x * blockDim.x + threadIdx.x;  // MTOT*DI/16 thr
    if (idx >= MTOT * DI / 16) return;
    const int ND4 = DI / 4;
    const int d4  = (idx & (ND4 - 1)) * 4;
    const int ml  = (idx / ND4) * 4;
    const int l   = ml & (SEQ - 1);

    float4 wt[4];
#pragma unroll
    for (int e = 0; e < 4; e++) wt[e] = ((const float4*)w)[d4 + e];
    const float4 bcv = *(const float4*)(bconv + d4);
    const float bias[4] = {bcv.x, bcv.y, bcv.z, bcv.w};

    float win[7][4];
#pragma unroll
    for (int j = 0; j < 7; j++) {
        const int lt = l - 3 + j;
        if (lt >= 0) {
            float4 v = *(const float4*)(xz + (size_t)(ml - 3 + j) * (2 * DI) + d4);
            win[j][0] = v.x; win[j][1] = v.y; win[j][2] = v.z; win[j][3] = v.w;
        } else {
            win[j][0] = win[j][1] = win[j][2] = win[j][3] = 0.f;
        }
    }

#pragma unroll
    for (int t = 0; t < 4; t++) {
        float o[4];
#pragma unroll
        for (int e = 0; e < 4; e++) {
            const float* wk = &wt[e].x;
            float acc = bias[e];
#pragma unroll
            for (int k = 0; k < 4; k++)
                acc += win[t + k][e] * wk[k];
            o[e] = acc / (1.f + __expf(-acc));
        }
        const size_t row = (size_t)(ml + t) * DI + d4;
        bf162 h0, h1, l0, l1;
        split2(o[0], o[1], h0, l0);
        split2(o[2], o[3], h1, l1);
        *(bf162*)(xchi + row)     = h0;  *(bf162*)(xchi + row + 2) = h1;
        *(bf162*)(xclo + row)     = l0;  *(bf162*)(xclo + row + 2) = l1;
    }
}

// ---------------------------------------------------------------------------
// Scan pass A  (xconv reconstructed from hi/lo; B cols from bc, stride 32)
// ---------------------------------------------------------------------------
__global__ void __launch_bounds__(256) scan_passA(
    const bf16* __restrict__ xchi, const bf16* __restrict__ xclo,
    const float* __restrict__ delta,
    const float* __restrict__ bc,    const float* __restrict__ A_log,
    float* __restrict__ chA, float* __restrict__ chH)
{
    __shared__ float Bsm[CHUNK][DS];
    const int d = blockIdx.x * blockDim.x + threadIdx.x;
    const int c = blockIdx.y, b = blockIdx.z;

    for (int i = threadIdx.x; i < CHUNK * DS; i += blockDim.x) {
        const int t = i >> 4, s = i & 15;
        Bsm[t][s] = bc[(size_t)(b * SEQ + c * CHUNK + t) * 32 + s];
    }
    __syncthreads();

    float Aa[DS], st[DS], cum[DS];
#pragma unroll
    for (int s = 0; s < DS; s++) {
        Aa[s]  = -expf(A_log[d * DS + s]);
        st[s]  = 0.f;
        cum[s] = 1.f;
    }
    const size_t base = (size_t)(b * SEQ + c * CHUNK) * DI + d;
    for (int t = 0; t < CHUNK; t++) {
        const float dt = delta[base + (size_t)t * DI];
        const float xv = __bfloat162float(xchi[base + (size_t)t * DI])
                       + __bfloat162float(xclo[base + (size_t)t * DI]);
#pragma unroll
        for (int s = 0; s < DS; s++) {
            const float dec = __expf(dt * Aa[s]);
            cum[s] *= dec;
            st[s]   = dec * st[s] + Bsm[t][s] * xv;
        }
    }
    const size_t o = ((size_t)(b * NCH + c) * DI + d) * DS;
#pragma unroll
    for (int s = 0; s < DS; s++) { chA[o + s] = cum[s]; chH[o + s] = st[s]; }
}

// ---------------------------------------------------------------------------
// Scan pass B
// ---------------------------------------------------------------------------
__global__ void scan_passB(const float* __restrict__ chA,
                           const float* __restrict__ chH,
                           float* __restrict__ hInit)
{
    const int idx = blockIdx.x * blockDim.x + threadIdx.x;
    if (idx >= BATCH * DI) return;
    const int b = idx / DI, d = idx % DI;
    float h[DS];
#pragma unroll
    for (int s = 0; s < DS; s++) h[s] = 0.f;
    for (int c = 0; c < NCH; c++) {
        const size_t o = ((size_t)(b * NCH + c) * DI + d) * DS;
#pragma unroll
        for (int s = 0; s < DS; s++) hInit[o + s] = h[s];
#pragma unroll
        for (int s = 0; s < DS; s++) h[s] = chA[o + s] * h[s] + chH[o + s];
    }
}

// ---------------------------------------------------------------------------
// Scan pass C: replay + C-contraction + D-skip + y*silu(z); writes yg hi/lo.
// ---------------------------------------------------------------------------
__global__ void __launch_bounds__(256) scan_passC(
    const bf16* __restrict__ xchi, const bf16* __restrict__ xclo,
    const float* __restrict__ delta,
    const float* __restrict__ bc,    const float* __restrict__ A_log,
    const float* __restrict__ Dv,    const float* __restrict__ xz,
    const float* __restrict__ hInit,
    bf16* __restrict__ yghi, bf16* __restrict__ yglo)
{
    __shared__ float Bsm[CHUNK][DS];
    __shared__ float Csm[CHUNK][DS];
    const int d = blockIdx.x * blockDim.x + threadIdx.x;
    const int c = blockIdx.y, b = blockIdx.z;

    for (int i = threadIdx.x; i < CHUNK * DS; i += blockDim.x) {
        const int t = i >> 4, s = i & 15;
        const size_t row = (size_t)(b * SEQ + c * CHUNK + t) * 32;
        Bsm[t][s] = bc[row + s];
        Csm[t][s] = bc[row + 16 + s];
    }
    __syncthreads();

    float Aa[DS], st[DS];
    const size_t o = ((size_t)(b * NCH + c) * DI + d) * DS;
#pragma unroll
    for (int s = 0; s < DS; s++) {
        Aa[s] = -expf(A_log[d * DS + s]);
        st[s] = hInit[o + s];
    }
    const float Dd = Dv[d];
    const size_t base = (size_t)(b * SEQ + c * CHUNK) * DI + d;
    for (int t = 0; t < CHUNK; t++) {
        const float dt = delta[base + (size_t)t * DI];
        const float xv = __bfloat162float(xchi[base + (size_t)t * DI])
                       + __bfloat162float(xclo[base + (size_t)t * DI]);
        float y = 0.f;
#pragma unroll
        for (int s = 0; s < DS; s++) {
            const float dec = __expf(dt * Aa[s]);
            st[s] = dec * st[s] + Bsm[t][s] * xv;
            y += st[s] * Csm[t][s];
        }
        y += Dd * xv;
        const float z = xz[(size_t)(b * SEQ + c * CHUNK + t) * (2 * DI) + DI + d];
        const float sg = 1.f / (1.f + __expf(-z));
        const float v = y * (z * sg);
        const size_t oi = base + (size_t)t * DI;
        bf16 h = __float2bfloat16(v);
        yghi[oi] = h;
        yglo[oi] = __float2bfloat16(v - __bfloat162float(h));
    }
}

// ---------------------------------------------------------------------------
template<int MODE>
static void launch_hgemm(const bf16* Ahi, const bf16* Alo, int lda,
                         const bf16* Whi, const bf16* Wlo,
                         const float* bias, float* C, int ldc,
                         bf16* Chi, bf16* Clo, int M, int N, int K)
{
    dim3 grid((N + 127) / 128, M / 128);
    cudaFuncSetAttribute(hgemm_bf<MODE>,
        cudaFuncAttributeMaxDynamicSharedMemorySize, GEMM_SMEM);
    hgemm_bf<MODE><<<grid, GTHREADS, GEMM_SMEM>>>(Ahi, Alo, lda, Whi, Wlo,
                                                  bias, C, ldc, Chi, Clo, M, N, K);
}

extern "C" void kernel_launch(void* const* d_in, const int* in_sizes, int n_in,
                              void* d_out, int out_size)
{
    const float* x      = (const float*)d_in[0];
    const float* W_in   = (const float*)d_in[1];
    const float* w_conv = (const float*)d_in[2];
    const float* b_conv = (const float*)d_in[3];
    const float* W_x    = (const float*)d_in[4];
    const float* W_dt   = (const float*)d_in[5];
    const float* b_dt   = (const float*)d_in[6];
    const float* A_log  = (const float*)d_in[7];
    const float* Dv     = (const float*)d_in[8];
    const float* W_out  = (const float*)d_in[9];
    float* out = (float*)d_out;

    float *xz, *delta, *bc, *chA, *chH, *hInit;
    cudaGetSymbolAddress((void**)&xz,    g_xz);
    cudaGetSymbolAddress((void**)&delta, g_delta);
    cudaGetSymbolAddress((void**)&bc,    g_bc);
    cudaGetSymbolAddress((void**)&chA,   g_chA);
    cudaGetSymbolAddress((void**)&chH,   g_chH);
    cudaGetSymbolAddress((void**)&hInit, g_hInit);

    bf16 *x_hi, *x_lo, *Win_hi, *Win_lo, *Wdt_hi, *Wdt_lo, *Wout_hi, *Wout_lo,
         *WxdT_hi, *WxdT_lo, *Wcomb_hi, *Wcomb_lo, *xc_hi, *xc_lo, *yg_hi, *yg_lo;
    cudaGetSymbolAddress((void**)&x_hi,     g_x_hi);
    cudaGetSymbolAddress((void**)&x_lo,     g_x_lo);
    cudaGetSymbolAddress((void**)&Win_hi,   g_Win_hi);
    cudaGetSymbolAddress((void**)&Win_lo,   g_Win_lo);
    cudaGetSymbolAddress((void**)&Wdt_hi,   g_Wdt_hi);
    cudaGetSymbolAddress((void**)&Wdt_lo,   g_Wdt_lo);
    cudaGetSymbolAddress((void**)&Wout_hi,  g_Wout_hi);
    cudaGetSymbolAddress((void**)&Wout_lo,  g_Wout_lo);
    cudaGetSymbolAddress((void**)&WxdT_hi,  g_WxdT_hi);
    cudaGetSymbolAddress((void**)&WxdT_lo,  g_WxdT_lo);
    cudaGetSymbolAddress((void**)&Wcomb_hi, g_Wcomb_hi);
    cudaGetSymbolAddress((void**)&Wcomb_lo, g_Wcomb_lo);
    cudaGetSymbolAddress((void**)&xc_hi,    g_xc_hi);
    cudaGetSymbolAddress((void**)&xc_lo,    g_xc_lo);
    cudaGetSymbolAddress((void**)&yg_hi,    g_yg_hi);
    cudaGetSymbolAddress((void**)&yg_lo,    g_yg_lo);

    // [0] preprocessing: transpose Wxd + split of x, W_in, W_dt, W_out
    {
        int n0 = MTOT * DM / 4;
        int n1 = (2 * DI) * DM / 4;
        int n2 = DI * DI / 4;
        int n3 = DM * DI / 4;
        int tot = n0 + n1 + n2 + n3;
        int blocks = NTRANS + (tot + 255) / 256;
        preproc_kernel<<<blocks, 256>>>(
            W_x, WxdT_hi, WxdT_lo,
            x, x_hi, x_lo, n0,
            W_in, Win_hi, Win_lo, n1,
            W_dt, Wdt_hi, Wdt_lo, n2,
            W_out, Wout_hi, Wout_lo, n3);
    }
    // [1] fused: GEMM1 (xz = x @ W_in^T) + Wcomb = Wdt @ Wxd
    {
        const int gx0 = (2 * DI) / 128, gy0 = MTOT / 128;   // 32 x 32
        const int gx1 = DI / 128;                            // 16 (gy1 = 16)
        const int total = gx0 * gy0 + gx1 * (DI / 128);
        cudaFuncSetAttribute(hgemm_dual,
            cudaFuncAttributeMaxDynamicSharedMemorySize, GEMM_SMEM);
        hgemm_dual<<<total, GTHREADS, GEMM_SMEM>>>(
            x_hi, x_lo, DM, Win_hi, Win_lo, xz, 2 * DI, MTOT, 2 * DI, DM, gx0, gy0,
            Wdt_hi, Wdt_lo, DI, WxdT_hi, WxdT_lo, Wcomb_hi, Wcomb_lo, DI,
            DI, DI, DI, gx1);
    }
    // [2] depthwise causal conv + silu (sliding window, hi/lo only)
    {
        int n = MTOT * DI / 16;
        conv_silu_kernel<<<(n + 255) / 256, 256>>>(xz, w_conv, b_conv,
                                                   xc_hi, xc_lo);
    }
    // [3] fused: delta = softplus(xconv @ Wcomb^T + b_dt)  +  bc columns
    {
        const int gx0 = DI / 128, gy0 = MTOT / 128;          // 16 x 32 = 512
        const int total = gx0 * gy0 + MTOT / BCROWS;         // + 256 bc blocks
        cudaFuncSetAttribute(hgemm_delta_bc,
            cudaFuncAttributeMaxDynamicSharedMemorySize, GEMM_SMEM);
        hgemm_delta_bc<<<total, GTHREADS, GEMM_SMEM>>>(
            xc_hi, xc_lo, Wcomb_hi, Wcomb_lo, b_dt, delta, W_x, bc, gx0, gy0);
    }
    // [4-6] chunked selective scan
    {
        dim3 gridA(DI / 256, NCH, BATCH);
        scan_passA<<<gridA, 256>>>(xc_hi, xc_lo, delta, bc, A_log, chA, chH);
        scan_passB<<<(BATCH * DI + 255) / 256, 256>>>(chA, chH, hInit);
        scan_passC<<<gridA, 256>>>(xc_hi, xc_lo, delta, bc, A_log, Dv, xz,
                                   hInit, yg_hi, yg_lo);
    }
    // [7] out = yg @ W_out^T
    launch_hgemm<0>(yg_hi, yg_lo, DI, Wout_hi, Wout_lo, nullptr,
                    out, DM, nullptr, nullptr, MTOT, DM, DI);
}